// round 3
// baseline (speedup 1.0000x reference)
#include <cuda_runtime.h>

#define HIDDEN 51
#define JP 64
#define KQ 13            // k-rows per quarter (4*13 = 52 = 51 real + bias row 51)
#define KREG 10          // k-rows held in registers
#define KSM (KQ - KREG)  // k-rows from smem table (3)
#define L_SEQ 1000
#define NBLK 128
#define THREADS 512      // 2 groups x 256; group = 4 batches

typedef unsigned long long ull;

// Gate-interleaved weights: g_U4[row*JP + j] = (i,f,g,o); row 51 = combined bias
__device__ float4 g_U4[52 * JP];
__device__ float4 g_W4[JP];   // x weights per j
__device__ float  g_L[JP];    // lin_w per j

// ---------- f32x2 helpers ----------
__device__ __forceinline__ ull pk2(float lo, float hi) {
    ull r; asm("mov.b64 %0, {%1, %2};" : "=l"(r) : "f"(lo), "f"(hi)); return r;
}
__device__ __forceinline__ void up2(float& lo, float& hi, ull v) {
    asm("mov.b64 {%0, %1}, %2;" : "=f"(lo), "=f"(hi) : "l"(v));
}
__device__ __forceinline__ ull f2fma(ull a, ull b, ull c) {
    ull d; asm("fma.rn.f32x2 %0, %1, %2, %3;" : "=l"(d) : "l"(a), "l"(b), "l"(c)); return d;
}
__device__ __forceinline__ ull f2add(ull a, ull b) {
    ull d; asm("add.rn.f32x2 %0, %1, %2;" : "=l"(d) : "l"(a), "l"(b)); return d;
}
__device__ __forceinline__ ull shfl_xor64(ull v, int m) {
    unsigned lo, hi;
    asm("mov.b64 {%0,%1}, %2;" : "=r"(lo), "=r"(hi) : "l"(v));
    lo = __shfl_xor_sync(0xffffffffu, lo, m);
    hi = __shfl_xor_sync(0xffffffffu, hi, m);
    ull r; asm("mov.b64 %0, {%1,%2};" : "=l"(r) : "r"(lo), "r"(hi));
    return r;
}
// accurate fast tanh: 1 - 2/(exp(2x)+1); saturates correctly at +-inf
__device__ __forceinline__ float fast_tanh(float xv) {
    float e;
    asm("ex2.approx.f32 %0, %1;" : "=f"(e) : "f"(xv * 2.8853900817779268f));
    float r;
    asm("rcp.approx.f32 %0, %1;" : "=f"(r) : "f"(e + 1.0f));
    return fmaf(-2.0f, r, 1.0f);
}
__device__ __forceinline__ void group_bar(int barid) {
    asm volatile("bar.sync %0, %1;" :: "r"(barid), "r"(256) : "memory");
}

// ---------- prep ----------
__global__ void prep_kernel(const float* __restrict__ W_w, const float* __restrict__ W_b,
                            const float* __restrict__ U_w, const float* __restrict__ U_b,
                            const float* __restrict__ lin_w) {
    int i = blockIdx.x * 128 + threadIdx.x;   // 0 .. 3327 (52 rows x 64 j)
    int k = i >> 6, j = i & 63;
    float4 u = make_float4(0.f, 0.f, 0.f, 0.f);
    if (j < HIDDEN) {
        if (k < HIDDEN) {
            u.x = U_w[(0 * HIDDEN + j) * HIDDEN + k];
            u.y = U_w[(1 * HIDDEN + j) * HIDDEN + k];
            u.z = U_w[(2 * HIDDEN + j) * HIDDEN + k];
            u.w = U_w[(3 * HIDDEN + j) * HIDDEN + k];
        } else if (k == HIDDEN) {             // row 51 = combined bias (h[51] == 1)
            u.x = W_b[0 * HIDDEN + j] + U_b[0 * HIDDEN + j];
            u.y = W_b[1 * HIDDEN + j] + U_b[1 * HIDDEN + j];
            u.z = W_b[2 * HIDDEN + j] + U_b[2 * HIDDEN + j];
            u.w = W_b[3 * HIDDEN + j] + U_b[3 * HIDDEN + j];
        }
    }
    g_U4[i] = u;
    if (i < JP) {
        float4 w = make_float4(0.f, 0.f, 0.f, 0.f);
        float lw = 0.f;
        if (i < HIDDEN) {
            w.x = W_w[0 * HIDDEN + i]; w.y = W_w[1 * HIDDEN + i];
            w.z = W_w[2 * HIDDEN + i]; w.w = W_w[3 * HIDDEN + i];
            lw = lin_w[i];
        }
        g_W4[i] = w; g_L[i] = lw;
    }
}

// ---------- main ----------
// 512 threads = 2 groups of 256. Group: 4 batches.
// lane = q*8 + j8 (q = k-quarter 0..3), j = wg*8 + j8 (wg 0..7 in group).
__global__ void __launch_bounds__(THREADS, 1)
lstm_main(const float* __restrict__ x, const float* __restrict__ lin_b,
          float* __restrict__ out) {
    __shared__ __align__(16) float h_sh[2][2][JP][4];   // [group][buf][row][batch]
    __shared__ __align__(16) ull   Ux[KSM * 4][JP][4];  // dup'd U rows 10..12 per quarter
    __shared__ float redp[2][2][8][4];                  // [group][buf][warp][batch]

    const int tid  = threadIdx.x;
    const int g    = tid >> 8;
    const int gtid = tid & 255;
    const int wg   = gtid >> 5;
    const int lane = tid & 31;
    const int q    = lane >> 3;
    const int j8   = lane & 7;
    const int j    = wg * 8 + j8;
    const int q0   = q & 1;
    const int q1   = q >> 1;
    const int b0   = blockIdx.x * 8 + g * 4;

    // U rows q*13 .. q*13+9 in registers, duplicated pairs per gate
    ull ud[KREG][4];
#pragma unroll
    for (int kk = 0; kk < KREG; kk++) {
        float4 u = g_U4[(q * KQ + kk) * JP + j];
        ud[kk][0] = pk2(u.x, u.x);
        ud[kk][1] = pk2(u.y, u.y);
        ud[kk][2] = pk2(u.z, u.z);
        ud[kk][3] = pk2(u.w, u.w);
    }
    // smem dup table for rows q*13+10 .. q*13+12
    for (int i = tid; i < KSM * 4 * JP; i += THREADS) {
        int r12 = i >> 6, jj = i & 63;
        int qq = r12 / KSM, e = r12 - qq * KSM;
        float4 u = g_U4[(qq * KQ + KREG + e) * JP + jj];
        Ux[r12][jj][0] = pk2(u.x, u.x);
        Ux[r12][jj][1] = pk2(u.y, u.y);
        Ux[r12][jj][2] = pk2(u.z, u.z);
        Ux[r12][jj][3] = pk2(u.w, u.w);
    }
    // h init: zeros, except row 51 == 1 (bias row), both groups/buffers
    for (int i = tid; i < 2 * 2 * JP * 4; i += THREADS) {
        int row = (i >> 2) & 63;
        ((float*)h_sh)[i] = (row == HIDDEN) ? 1.0f : 0.0f;
    }

    float4 wv = g_W4[j];
    const float lw  = g_L[j];
    const float lbv = lin_b[0];

    float c  = 0.f;                               // cell state for (j, batch q)
    float xq = x[(b0 + q) * L_SEQ + 0];           // x for my batch, t=0

    __syncthreads();

    for (int t = 0; t < L_SEQ; ++t) {
        const int rb = t & 1, wb = rb ^ 1, tb = t & 1;

        // ---- phase A: partial gates over my 13 k-rows, batch-paired f32x2 ----
        ull a[4][2];
#pragma unroll
        for (int gi = 0; gi < 4; gi++) { a[gi][0] = 0ULL; a[gi][1] = 0ULL; }

        const float4* hrow = (const float4*)h_sh[g][rb] + q * KQ;
#pragma unroll
        for (int kk = 0; kk < KREG; kk++) {
            float4 hq = hrow[kk];
            ull h01 = pk2(hq.x, hq.y);
            ull h23 = pk2(hq.z, hq.w);
            a[0][0] = f2fma(h01, ud[kk][0], a[0][0]); a[0][1] = f2fma(h23, ud[kk][0], a[0][1]);
            a[1][0] = f2fma(h01, ud[kk][1], a[1][0]); a[1][1] = f2fma(h23, ud[kk][1], a[1][1]);
            a[2][0] = f2fma(h01, ud[kk][2], a[2][0]); a[2][1] = f2fma(h23, ud[kk][2], a[2][1]);
            a[3][0] = f2fma(h01, ud[kk][3], a[3][0]); a[3][1] = f2fma(h23, ud[kk][3], a[3][1]);
        }
#pragma unroll
        for (int e = 0; e < KSM; e++) {
            float4 hq = hrow[KREG + e];
            ull h01 = pk2(hq.x, hq.y);
            ull h23 = pk2(hq.z, hq.w);
            const ull* ux = Ux[q * KSM + e][j];
            ulonglong2 u01 = *(const ulonglong2*)&ux[0];
            ulonglong2 u23 = *(const ulonglong2*)&ux[2];
            a[0][0] = f2fma(h01, u01.x, a[0][0]); a[0][1] = f2fma(h23, u01.x, a[0][1]);
            a[1][0] = f2fma(h01, u01.y, a[1][0]); a[1][1] = f2fma(h23, u01.y, a[1][1]);
            a[2][0] = f2fma(h01, u23.x, a[2][0]); a[2][1] = f2fma(h23, u23.x, a[2][1]);
            a[3][0] = f2fma(h01, u23.y, a[3][0]); a[3][1] = f2fma(h23, u23.y, a[3][1]);
        }

        // prefetch next x (hidden under exchange/update)
        float xn = x[(b0 + q) * L_SEQ + ((t + 1 < L_SEQ) ? t + 1 : t)];

        // ---- exchange: reduce over 4 quarters, specialize to batch q ----
        float gate[4];
#pragma unroll
        for (int gi = 0; gi < 4; gi++) {
            ull s = q1 ? a[gi][0] : a[gi][1];      // send the pair I don't keep
            ull r = shfl_xor64(s, 16);
            ull p = f2add(q1 ? a[gi][1] : a[gi][0], r);
            r = shfl_xor64(p, 8);
            p = f2add(p, r);                       // both slots = full sums (pair q1)
            float lo, hi; up2(lo, hi, p);
            gate[gi] = q0 ? hi : lo;               // batch = 2*q1 + q0 = q
        }

        // ---- update c/h for (j, batch q) ----
        float gi_ = fmaf(xq, wv.x, gate[0]);
        float gf_ = fmaf(xq, wv.y, gate[1]);
        float gg_ = fmaf(xq, wv.z, gate[2]);
        float go_ = fmaf(xq, wv.w, gate[3]);
        c = fmaf(gf_, c, gi_ * gg_);               // no sigmoids (faithful)
        float h = go_ * fast_tanh(c);
        if (j == HIDDEN) h = 1.0f;                 // maintain bias row
        h_sh[g][wb][j][q] = h;

        float prod = h * lw;
        prod += __shfl_xor_sync(0xffffffffu, prod, 1);
        prod += __shfl_xor_sync(0xffffffffu, prod, 2);
        prod += __shfl_xor_sync(0xffffffffu, prod, 4);
        if (j8 == 0) redp[g][tb][wg][q] = prod;

        xq = xn;
        group_bar(g + 1);

        // ---- output for step t ----
        if (gtid < 4) {
            int b = gtid;
            float v = lbv;
#pragma unroll
            for (int w = 0; w < 8; w++) v += redp[g][tb][w][b];
            out[(b0 + b) * L_SEQ + t] = v;
        }
    }
}

extern "C" void kernel_launch(void* const* d_in, const int* in_sizes, int n_in,
                              void* d_out, int out_size) {
    (void)in_sizes; (void)n_in; (void)out_size;
    const float* x     = (const float*)d_in[0];
    const float* W_w   = (const float*)d_in[1];
    const float* W_b   = (const float*)d_in[2];
    const float* U_w   = (const float*)d_in[3];
    const float* U_b   = (const float*)d_in[4];
    const float* lin_w = (const float*)d_in[5];
    const float* lin_b = (const float*)d_in[6];
    // d_in[7] = future (static 0) — ignored.

    prep_kernel<<<26, 128>>>(W_w, W_b, U_w, U_b, lin_w);
    lstm_main<<<NBLK, THREADS>>>(x, lin_b, (float*)d_out);
}